// round 1
// baseline (speedup 1.0000x reference)
#include <cuda_runtime.h>
#include <math.h>

// Problem constants (fixed by the dataset: logits [64,128,32000] fp32)
#define BB 64
#define TT 128
#define VV 32000
#define SPLIT 4            // blocks per row
#define THREADS 256
#define EOS_IDX 2
#define BONUS_WEIGHT 0.1f

// Scratch in __device__ globals (no allocations allowed).
// Fully overwritten by kernel A every call before kernel B reads -> deterministic.
__device__ float g_pm[BB * SPLIT];   // partial max per (b, split)
__device__ float g_ps[BB * SPLIT];   // partial sum-exp per (b, split)
__device__ float g_x2[BB];           // logits[b, eos_pos, EOS_IDX]

// -------- Kernel A: per-(row, split) online softmax partials --------
__global__ __launch_bounds__(THREADS)
void eos_row_pass(const float* __restrict__ logits,
                  const int* __restrict__ lengths) {
    const int bid = blockIdx.x;
    const int b = bid / SPLIT;
    const int s = bid % SPLIT;

    const int len = lengths[b];
    int pos = len - 1;
    pos = pos < 0 ? 0 : (pos > TT - 1 ? TT - 1 : pos);

    const float* row = logits + ((size_t)b * TT + pos) * VV;

    if (s == 0 && threadIdx.x == 0) {
        g_x2[b] = row[EOS_IDX];
    }

    const int chunk = VV / SPLIT;            // 8000
    const float4* row4 = (const float4*)(row + s * chunk);
    const int n4 = chunk / 4;                // 2000

    // Per-thread online (max, sum-exp)
    float m = -INFINITY;
    float sum = 0.0f;
    for (int i = threadIdx.x; i < n4; i += THREADS) {
        float4 v = row4[i];
        float lm = fmaxf(fmaxf(v.x, v.y), fmaxf(v.z, v.w));
        if (lm > m) {
            sum *= __expf(m - lm);   // m=-inf on first hit -> exp(-inf)=0, sum stays 0
            m = lm;
        }
        sum += __expf(v.x - m) + __expf(v.y - m) + __expf(v.z - m) + __expf(v.w - m);
    }

    // Warp reduce (m, sum)
    #pragma unroll
    for (int off = 16; off > 0; off >>= 1) {
        float om = __shfl_down_sync(0xffffffffu, m, off);
        float os = __shfl_down_sync(0xffffffffu, sum, off);
        float M = fmaxf(m, om);
        sum = sum * __expf(m - M) + os * __expf(om - M);
        m = M;
    }

    // Block reduce across warps
    __shared__ float sm_m[THREADS / 32];
    __shared__ float sm_s[THREADS / 32];
    const int lane = threadIdx.x & 31;
    const int wid = threadIdx.x >> 5;
    if (lane == 0) { sm_m[wid] = m; sm_s[wid] = sum; }
    __syncthreads();
    if (wid == 0) {
        const int nw = THREADS / 32;
        m = (lane < nw) ? sm_m[lane] : -INFINITY;
        sum = (lane < nw) ? sm_s[lane] : 0.0f;
        #pragma unroll
        for (int off = 4; off > 0; off >>= 1) {
            float om = __shfl_down_sync(0xffffffffu, m, off);
            float os = __shfl_down_sync(0xffffffffu, sum, off);
            float M = fmaxf(m, om);
            sum = sum * __expf(m - M) + os * __expf(om - M);
            m = M;
        }
        if (lane == 0) {
            g_pm[bid] = m;
            g_ps[bid] = sum;
        }
    }
}

// -------- Kernel B: merge splits, compute prob, mask, reduce over B --------
__global__ void eos_finalize(const int* __restrict__ lengths,
                             float* __restrict__ out) {
    const int t = threadIdx.x;     // 64 threads, one per batch row
    float prob = 0.0f;
    if (t < BB) {
        float m = -INFINITY, sum = 0.0f;
        #pragma unroll
        for (int s = 0; s < SPLIT; s++) {
            float om = g_pm[t * SPLIT + s];
            float os = g_ps[t * SPLIT + s];
            float M = fmaxf(m, om);
            sum = sum * __expf(m - M) + os * __expf(om - M);
            m = M;
        }
        float lse = m + logf(sum);
        float p = expf(g_x2[t] - lse);
        int len = lengths[t];
        bool valid = (len > 1) && ((len - 1) < TT);
        prob = valid ? p : 0.0f;
    }

    // Reduce 64 values (2 warps)
    #pragma unroll
    for (int off = 16; off > 0; off >>= 1)
        prob += __shfl_down_sync(0xffffffffu, prob, off);

    __shared__ float sm[2];
    const int lane = threadIdx.x & 31;
    const int wid = threadIdx.x >> 5;
    if (lane == 0) sm[wid] = prob;
    __syncthreads();
    if (t == 0) {
        float total = sm[0] + sm[1];
        *out = -(total * BONUS_WEIGHT) / (float)BB;
    }
}

extern "C" void kernel_launch(void* const* d_in, const int* in_sizes, int n_in,
                              void* d_out, int out_size) {
    const float* logits = (const float*)d_in[0];
    // d_in[1] = targets (unused by the reference math)
    const int* lengths = (const int*)d_in[2];
    float* out = (float*)d_out;

    eos_row_pass<<<BB * SPLIT, THREADS>>>(logits, lengths);
    eos_finalize<<<1, 64>>>(lengths, out);
}